// round 7
// baseline (speedup 1.0000x reference)
#include <cuda_runtime.h>
#include <cuda_bf16.h>
#include <math.h>

#define NN   50000
#define EE   600000
#define D    128
#define OUTD 64
#define NBLK ((NN + 255) / 256)

// ---------------- scratch (device globals; no allocation) ----------------
__device__ int      g_is64;
__device__ int      g_cnt[NN];
__device__ int      g_part[NBLK];
__device__ int      g_off[NN + 1];
__device__ int      g_fill[NN + 1];
__device__ int      g_csr_src[EE];
__device__ float    g_ew[EE];
__device__ float    g_h   [(size_t)NN * D];
__device__ float    g_bufA[(size_t)NN * D];
__device__ float    g_si[NN];
__device__ float    g_sj[NN];
__device__ float    g_Wc[D * OUTD];
__device__ float    g_bc[OUTD];

// ---------------- detect dtype + zero histogram ----------------
__global__ void k_detect(const void* ei) {
    int i = blockIdx.x * 256 + threadIdx.x;
    if (i < NN) g_cnt[i] = 0;
    if (blockIdx.x == 0 && threadIdx.x < 32) {
        const long long* p = (const long long*)ei;
        long long v = p[threadIdx.x];
        int bad = (v < 0 || v >= NN) ? 1 : 0;
        unsigned b = __ballot_sync(0xffffffffu, bad);
        if (threadIdx.x == 0) g_is64 = (b == 0) ? 1 : 0;
    }
}

__device__ __forceinline__ void load_edge(const void* ei, int i, int& s, int& d) {
    if (g_is64) {
        const long long* p = (const long long*)ei;
        s = (int)p[i];
        d = (int)p[(size_t)EE + i];
    } else {
        const int* p = (const int*)ei;
        s = p[i];
        d = p[EE + i];
    }
}

__global__ void k_hist(const void* ei) {
    int i = blockIdx.x * blockDim.x + threadIdx.x;
    if (i >= EE) return;
    int d;
    if (g_is64) {
        const long long* p = (const long long*)ei;
        d = (int)p[(size_t)EE + i];
    } else {
        const int* p = (const int*)ei;
        d = p[EE + i];
    }
    atomicAdd(&g_cnt[d], 1);
}

// ---------------- scan: per-block sums, then per-block scan with inline base ----------------
__global__ void k_scanA() {
    __shared__ int sw[8];
    int b = blockIdx.x;
    int i = b * 256 + threadIdx.x;
    int v = (i < NN) ? g_cnt[i] : 0;
    int lane = threadIdx.x & 31, wid = threadIdx.x >> 5;
#pragma unroll
    for (int o = 16; o > 0; o >>= 1) v += __shfl_xor_sync(0xffffffffu, v, o);
    if (lane == 0) sw[wid] = v;
    __syncthreads();
    if (threadIdx.x == 0) {
        int s = 0;
#pragma unroll
        for (int w = 0; w < 8; w++) s += sw[w];
        g_part[b] = s;
    }
}

__global__ void k_scanC() {
    __shared__ int sw[8];
    __shared__ int sbase;
    int b = blockIdx.x;
    int i = b * 256 + threadIdx.x;
    int lane = threadIdx.x & 31, wid = threadIdx.x >> 5;
    int v = (i < NN) ? g_cnt[i] : 0;
    int x = v;
#pragma unroll
    for (int o = 1; o < 32; o <<= 1) {
        int t = __shfl_up_sync(0xffffffffu, x, o);
        if (lane >= o) x += t;
    }
    if (lane == 31) sw[wid] = x;
    if (wid == 1) {            // warp 1 computes base = sum g_part[0..b-1]
        int s = 0;
        for (int j = lane; j < b; j += 32) s += g_part[j];
#pragma unroll
        for (int o = 16; o > 0; o >>= 1) s += __shfl_xor_sync(0xffffffffu, s, o);
        if (lane == 0) sbase = s;
    }
    __syncthreads();
    if (wid == 0 && lane < 8) {
        int y = sw[lane];
#pragma unroll
        for (int o = 1; o < 8; o <<= 1) {
            int t = __shfl_up_sync(0xffu, y, o);
            if (lane >= o) y += t;
        }
        sw[lane] = y;
    }
    __syncthreads();
    int incl = x + (wid ? sw[wid - 1] : 0) + sbase;
    if (i < NN) { g_off[i + 1] = incl; g_fill[i + 1] = incl; }
    if (i == 0) { g_off[0] = 0; g_fill[0] = 0; }
}

__global__ void k_reorder(const void* ei) {
    int i = blockIdx.x * blockDim.x + threadIdx.x;
    if (i >= EE) return;
    int s, d;
    load_edge(ei, i, s, d);
    int pos = atomicAdd(&g_fill[d], 1);
    g_csr_src[pos] = s;
}

// ---------------- GEMM 128x128 tile, 8x8/thread, double-buffered ----------------
__global__ void __launch_bounds__(256, 2)
k_gemm(const float* __restrict__ X, const float* __restrict__ W,
       const float* __restrict__ bias, const float* __restrict__ att,
       float* __restrict__ Y, int nrows) {
    __shared__ float Xs[2][16][132];
    __shared__ float Ws[2][16][132];
    int t = threadIdx.x;
    int row0 = blockIdx.x * 128;
    int tx = t & 15, ty = t >> 4;
    float acc[8][8];
#pragma unroll
    for (int i = 0; i < 8; i++)
#pragma unroll
        for (int j = 0; j < 8; j++) acc[i][j] = 0.f;

    int xr_r[2], xr_kq[2], wr_r[2], wr_cq[2];
#pragma unroll
    for (int l = 0; l < 2; l++) {
        int idx = t + l * 256;
        xr_r[l]  = idx >> 2;
        xr_kq[l] = (idx & 3) * 4;
        wr_r[l]  = idx >> 5;
        wr_cq[l] = (idx & 31) * 4;
    }

    float4 xv[2], wv[2];
#pragma unroll
    for (int l = 0; l < 2; l++) {
        int gr = row0 + xr_r[l];
        xv[l] = make_float4(0.f, 0.f, 0.f, 0.f);
        if (gr < nrows) xv[l] = *(const float4*)&X[(size_t)gr * D + xr_kq[l]];
        wv[l] = *(const float4*)&W[(size_t)wr_r[l] * D + wr_cq[l]];
    }
#pragma unroll
    for (int l = 0; l < 2; l++) {
        Xs[0][xr_kq[l] + 0][xr_r[l]] = xv[l].x;
        Xs[0][xr_kq[l] + 1][xr_r[l]] = xv[l].y;
        Xs[0][xr_kq[l] + 2][xr_r[l]] = xv[l].z;
        Xs[0][xr_kq[l] + 3][xr_r[l]] = xv[l].w;
        *(float4*)&Ws[0][wr_r[l]][wr_cq[l]] = wv[l];
    }
    __syncthreads();

    for (int kt = 0; kt < 8; kt++) {
        int cur = kt & 1;
        if (kt < 7) {
#pragma unroll
            for (int l = 0; l < 2; l++) {
                int gr = row0 + xr_r[l];
                xv[l] = make_float4(0.f, 0.f, 0.f, 0.f);
                if (gr < nrows) xv[l] = *(const float4*)&X[(size_t)gr * D + (kt + 1) * 16 + xr_kq[l]];
                wv[l] = *(const float4*)&W[(size_t)((kt + 1) * 16 + wr_r[l]) * D + wr_cq[l]];
            }
        }
#pragma unroll
        for (int kk = 0; kk < 16; kk++) {
            float4 a0 = *(float4*)&Xs[cur][kk][ty * 8];
            float4 a1 = *(float4*)&Xs[cur][kk][ty * 8 + 4];
            float4 w0 = *(float4*)&Ws[cur][kk][tx * 8];
            float4 w1 = *(float4*)&Ws[cur][kk][tx * 8 + 4];
            float a[8] = {a0.x, a0.y, a0.z, a0.w, a1.x, a1.y, a1.z, a1.w};
            float w[8] = {w0.x, w0.y, w0.z, w0.w, w1.x, w1.y, w1.z, w1.w};
#pragma unroll
            for (int i = 0; i < 8; i++)
#pragma unroll
                for (int j = 0; j < 8; j++)
                    acc[i][j] = fmaf(a[i], w[j], acc[i][j]);
        }
        if (kt < 7) {
            int nxt = 1 - cur;
#pragma unroll
            for (int l = 0; l < 2; l++) {
                Xs[nxt][xr_kq[l] + 0][xr_r[l]] = xv[l].x;
                Xs[nxt][xr_kq[l] + 1][xr_r[l]] = xv[l].y;
                Xs[nxt][xr_kq[l] + 2][xr_r[l]] = xv[l].z;
                Xs[nxt][xr_kq[l] + 3][xr_r[l]] = xv[l].w;
                *(float4*)&Ws[nxt][wr_r[l]][wr_cq[l]] = wv[l];
            }
            __syncthreads();
        }
    }

    float bj[8], ai[8], aj[8];
#pragma unroll
    for (int j = 0; j < 8; j++) {
        int c = tx * 8 + j;
        bj[j] = bias[c]; ai[j] = att[c]; aj[j] = att[D + c];
    }
#pragma unroll
    for (int i = 0; i < 8; i++) {
        int gr = row0 + ty * 8 + i;
#pragma unroll
        for (int j = 0; j < 8; j++) acc[i][j] += bj[j];
        if (gr < nrows) {
            float4 o0 = make_float4(acc[i][0], acc[i][1], acc[i][2], acc[i][3]);
            float4 o1 = make_float4(acc[i][4], acc[i][5], acc[i][6], acc[i][7]);
            *(float4*)&Y[(size_t)gr * D + tx * 8]     = o0;
            *(float4*)&Y[(size_t)gr * D + tx * 8 + 4] = o1;
        }
        float si = 0.f, sj = 0.f;
#pragma unroll
        for (int j = 0; j < 8; j++) {
            si = fmaf(acc[i][j], ai[j], si);
            sj = fmaf(acc[i][j], aj[j], sj);
        }
#pragma unroll
        for (int o = 1; o < 16; o <<= 1) {
            si += __shfl_xor_sync(0xffffffffu, si, o);
            sj += __shfl_xor_sync(0xffffffffu, sj, o);
        }
        if (tx == 0 && gr < nrows) { g_si[gr] = si; g_sj[gr] = sj; }
    }
}

// ---------------- fused edge kernel ----------------
#define WPB 8
__global__ void k_edge(const float* __restrict__ h, const float* __restrict__ bias,
                       float* __restrict__ out) {
    __shared__ float sAlpha[WPB][64];
    __shared__ int   sSrc[WPB][64];
    int wi = threadIdx.x >> 5;
    int node = blockIdx.x * WPB + wi;
    int lane = threadIdx.x & 31;
    int beg = g_off[node], end = g_off[node + 1];
    float4 b4 = ((const float4*)bias)[lane];
    if (beg >= end) {
        float4 o4 = make_float4(fmaxf(b4.x, 0.f), fmaxf(b4.y, 0.f),
                                fmaxf(b4.z, 0.f), fmaxf(b4.w, 0.f));
        ((float4*)out)[(size_t)node * 32 + lane] = o4;
        return;
    }
    float si_n = g_si[node];

    // pass 1: online softmax; stash e in g_ew
    float m = -1e30f, sum = 0.f;
    for (int i = beg + lane; i < end; i += 32) {
        int s = g_csr_src[i];
        float v = si_n + g_sj[s];
        float e = v > 0.f ? v : 0.2f * v;
        g_ew[i] = e;
        float mn = fmaxf(m, e);
        sum = sum * __expf(m - mn) + __expf(e - mn);
        m = mn;
    }
#pragma unroll
    for (int o = 16; o > 0; o >>= 1) {
        float mo = __shfl_xor_sync(0xffffffffu, m, o);
        float so = __shfl_xor_sync(0xffffffffu, sum, o);
        float mn = fmaxf(m, mo);
        sum = sum * __expf(m - mn) + so * __expf(mo - mn);
        m = mn;
    }
    float inv = 1.f / (sum + 1e-16f);

    // pass 2: alpha-weighted gather, uniform batches of 8 (alpha=0 padding)
    float4 acc = make_float4(0.f, 0.f, 0.f, 0.f);
    for (int base = beg; base < end; base += 64) {
        int cnt = min(64, end - base);
        int padded = (cnt + 7) & ~7;
        for (int i = lane; i < padded; i += 32) {
            if (i < cnt) {
                sSrc[wi][i]   = g_csr_src[base + i];
                sAlpha[wi][i] = __expf(g_ew[base + i] - m) * inv;
            } else {
                sSrc[wi][i]   = g_csr_src[base];
                sAlpha[wi][i] = 0.f;
            }
        }
        __syncwarp();
        for (int i = 0; i < padded; i += 8) {
            float4 hv[8]; float a[8];
#pragma unroll
            for (int j = 0; j < 8; j++) {
                a[j]  = sAlpha[wi][i + j];
                hv[j] = ((const float4*)h)[(size_t)sSrc[wi][i + j] * 32 + lane];
            }
#pragma unroll
            for (int j = 0; j < 8; j++) {
                acc.x = fmaf(a[j], hv[j].x, acc.x);
                acc.y = fmaf(a[j], hv[j].y, acc.y);
                acc.z = fmaf(a[j], hv[j].z, acc.z);
                acc.w = fmaf(a[j], hv[j].w, acc.w);
            }
        }
        __syncwarp();
    }
    float4 o4;
    o4.x = fmaxf(acc.x + b4.x, 0.f);
    o4.y = fmaxf(acc.y + b4.y, 0.f);
    o4.z = fmaxf(acc.z + b4.z, 0.f);
    o4.w = fmaxf(acc.w + b4.w, 0.f);
    ((float4*)out)[(size_t)node * 32 + lane] = o4;
}

// ---------------- combine final MLP ----------------
__global__ void k_combine(const float* __restrict__ Wp1, const float* __restrict__ bp1,
                          const float* __restrict__ Wp2, const float* __restrict__ bp2) {
    int c = blockIdx.x;
    int k = threadIdx.x;
    float s = 0.f;
    for (int mm = 0; mm < D; mm++) s = fmaf(Wp1[k * D + mm], Wp2[mm * OUTD + c], s);
    g_Wc[k * OUTD + c] = s;
    if (k == 0) {
        float b = bp2[c];
        for (int mm = 0; mm < D; mm++) b = fmaf(bp1[mm], Wp2[mm * OUTD + c], b);
        g_bc[c] = b;
    }
}

// ---------------- final GEMM + log_softmax ----------------
__global__ void __launch_bounds__(256, 4)
k_final(const float* __restrict__ x3, const float* __restrict__ Wc,
        const float* __restrict__ bc, float* __restrict__ out) {
    __shared__ float Xs[32][68];
    __shared__ float Ws[32][68];
    int t = threadIdx.x;
    int row0 = blockIdx.x * 64;
    int tx = t & 15, ty = t >> 4;
    float acc[4][4];
#pragma unroll
    for (int i = 0; i < 4; i++)
#pragma unroll
        for (int j = 0; j < 4; j++) acc[i][j] = 0.f;

    for (int kt = 0; kt < 4; kt++) {
#pragma unroll
        for (int l = 0; l < 2; l++) {
            int idx = t + l * 256;
            int r = idx >> 3;
            int kq = (idx & 7) * 4;
            int gr = row0 + r;
            float4 v = make_float4(0.f, 0.f, 0.f, 0.f);
            if (gr < NN) v = *(const float4*)&x3[(size_t)gr * D + kt * 32 + kq];
            Xs[kq + 0][r] = v.x; Xs[kq + 1][r] = v.y;
            Xs[kq + 2][r] = v.z; Xs[kq + 3][r] = v.w;
        }
#pragma unroll
        for (int l = 0; l < 2; l++) {
            int idx = t + l * 256;
            int r = idx >> 4;
            int cq = (idx & 15) * 4;
            *(float4*)&Ws[r][cq] = *(const float4*)&Wc[(size_t)(kt * 32 + r) * OUTD + cq];
        }
        __syncthreads();
#pragma unroll
        for (int kk = 0; kk < 32; kk++) {
            float4 av = *(float4*)&Xs[kk][ty * 4];
            float4 wv = *(float4*)&Ws[kk][tx * 4];
            float a[4] = {av.x, av.y, av.z, av.w};
            float w[4] = {wv.x, wv.y, wv.z, wv.w};
#pragma unroll
            for (int i = 0; i < 4; i++)
#pragma unroll
                for (int j = 0; j < 4; j++)
                    acc[i][j] = fmaf(a[i], w[j], acc[i][j]);
        }
        __syncthreads();
    }

    float b[4];
#pragma unroll
    for (int j = 0; j < 4; j++) b[j] = bc[tx * 4 + j];
#pragma unroll
    for (int i = 0; i < 4; i++) {
        float z[4];
        float m = -1e30f;
#pragma unroll
        for (int j = 0; j < 4; j++) { z[j] = acc[i][j] + b[j]; m = fmaxf(m, z[j]); }
#pragma unroll
        for (int o = 1; o < 16; o <<= 1) m = fmaxf(m, __shfl_xor_sync(0xffffffffu, m, o));
        float s = 0.f;
#pragma unroll
        for (int j = 0; j < 4; j++) s += __expf(z[j] - m);
#pragma unroll
        for (int o = 1; o < 16; o <<= 1) s += __shfl_xor_sync(0xffffffffu, s, o);
        float lg = m + __logf(s);
        int gr = row0 + ty * 4 + i;
        if (gr < NN) {
            float4 o4 = make_float4(z[0] - lg, z[1] - lg, z[2] - lg, z[3] - lg);
            *(float4*)&out[(size_t)gr * OUTD + tx * 4] = o4;
        }
    }
}

// ---------------- host launcher ----------------
extern "C" void kernel_launch(void* const* d_in, const int* in_sizes, int n_in,
                              void* d_out, int out_size) {
    const float* x      = (const float*)d_in[0];
    const void*  ei     = d_in[1];
    const float* Ws     = (const float*)d_in[2];
    const float* bs     = (const float*)d_in[3];
    const float* atts   = (const float*)d_in[4];
    const float* biases = (const float*)d_in[5];
    const float* Wp1    = (const float*)d_in[6];
    const float* bp1    = (const float*)d_in[7];
    const float* Wp2    = (const float*)d_in[8];
    const float* bp2    = (const float*)d_in[9];
    float* out = (float*)d_out;

    float *h, *bufA, *Wc, *bc;
    void* tmp;
    cudaGetSymbolAddress(&tmp, g_h);    h    = (float*)tmp;
    cudaGetSymbolAddress(&tmp, g_bufA); bufA = (float*)tmp;
    cudaGetSymbolAddress(&tmp, g_Wc);   Wc   = (float*)tmp;
    cudaGetSymbolAddress(&tmp, g_bc);   bc   = (float*)tmp;

    // launch indices: 0 detect, 1 hist, 2 scanA, 3 scanC, 4 reorder, 5 gemm(l0) <- ncu slot
    k_detect<<<NBLK, 256>>>(ei);
    k_hist<<<(EE + 255) / 256, 256>>>(ei);
    k_scanA<<<NBLK, 256>>>();
    k_scanC<<<NBLK, 256>>>();
    k_reorder<<<(EE + 255) / 256, 256>>>(ei);

    for (int l = 0; l < 3; l++) {
        const float* xin = (l == 0) ? x : bufA;
        k_gemm<<<(NN + 127) / 128, 256>>>(xin, Ws + (size_t)l * D * D, bs + l * D,
                                          atts + (size_t)l * 2 * D, h, NN);
        k_edge<<<NN / WPB, WPB * 32>>>(h, biases + l * D, bufA);
    }
    k_combine<<<OUTD, D>>>(Wp1, bp1, Wp2, bp2);
    k_final<<<(NN + 63) / 64, 256>>>(bufA, Wc, bc, out);
}